// round 1
// baseline (speedup 1.0000x reference)
#include <cuda_runtime.h>
#include <math.h>

#define N_SAMPLES 16384
#define IN_DIM    1024
#define HID       1024
#define OUT_DIM   64
#define LR        0.01f
#define EPSN      1e-8f

// Staging for results between kernels (no allocs allowed).
__device__ float g_p[IN_DIM];
__device__ float g_r[OUT_DIM];
__device__ float g_q;

__device__ __forceinline__ float sigmoidf(float z) {
    return 1.0f / (1.0f + expf(-z));
}

__device__ __forceinline__ float wredu(float v) {
#pragma unroll
    for (int o = 16; o; o >>= 1) v += __shfl_xor_sync(0xffffffffu, v, o);
    return v;
}

// Persistent single-block trainer. 128 threads, 4 warps.
// Invariant structure: w1 = p ⊗ 1, w2 = q * 1⊗1, w3 = 1 ⊗ r, b1=β1*1, b2=β2*1.
__global__ void __launch_bounds__(128, 1)
train_kernel(const float* __restrict__ X,      // [16384,1024]
             const float* __restrict__ T,      // [16384,64]
             const float* __restrict__ w1_in,
             const float* __restrict__ b1_in,
             const float* __restrict__ w2_in,
             const float* __restrict__ b2_in,
             const float* __restrict__ w3_in,
             const float* __restrict__ b3_in)
{
    __shared__ float red_s1[4], red_xx[4], red_pp[4];
    __shared__ float s_lam, s_wn;

    const int tid  = threadIdx.x;
    const int lane = tid & 31;
    const int warp = tid >> 5;

    // per-thread slice of p (8 contiguous elements), prev/cur x rows
    float p[8], xp[8], xc[8];
#pragma unroll
    for (int k = 0; k < 8; k++) {
        p[k]  = w1_in[(size_t)(tid * 8 + k) * HID];  // column 0 (columns identical)
        xp[k] = 0.0f;
        xc[k] = X[tid * 8 + k];                      // row 0
    }
    if (tid == 0) { s_lam = 0.0f; s_wn = 1.0f; }     // no pending update at t=0

    // warp-0 scalar / 64-dim state (2 elements per lane)
    float r0 = 0, r1 = 0, b30 = 0, b31 = 0, q = 0, be1 = 0, be2 = 0;
    float tg0 = 0, tg1 = 0;
    if (warp == 0) {
        r0  = w3_in[lane];       r1  = w3_in[32 + lane];   // row 0 of w3 (rows identical)
        b30 = b3_in[lane];       b31 = b3_in[32 + lane];
        q   = w2_in[0];          be1 = b1_in[0];           be2 = b2_in[0];
        tg0 = T[lane];           tg1 = T[32 + lane];
    }
    __syncthreads();

    for (int t = 0; t < N_SAMPLES; ++t) {
        // ---- phase A (all warps): apply pending p update, fused dot/norm reduce
        float lam = s_lam, wn = s_wn;
        float s1 = 0.0f, xx = 0.0f, pp = 0.0f;
#pragma unroll
        for (int k = 0; k < 8; k++) {
            float pk = (p[k] - lam * xp[k]) / wn;
            p[k] = pk;
            s1 = fmaf(xc[k], pk,    s1);   // x_t · p_t
            xx = fmaf(xc[k], xc[k], xx);   // ||x_t||^2
            pp = fmaf(pk,    pk,    pp);   // ||p_t||^2
            xp[k] = xc[k];
        }
        // prefetch next x row (latency hidden behind phase B)
        if (t + 1 < N_SAMPLES) {
            const float4* nx = (const float4*)(X + (size_t)(t + 1) * IN_DIM + tid * 8);
            float4 a = nx[0], b = nx[1];
            xc[0] = a.x; xc[1] = a.y; xc[2] = a.z; xc[3] = a.w;
            xc[4] = b.x; xc[5] = b.y; xc[6] = b.z; xc[7] = b.w;
        }
        s1 = wredu(s1); xx = wredu(xx); pp = wredu(pp);
        if (lane == 0) { red_s1[warp] = s1; red_xx[warp] = xx; red_pp[warp] = pp; }
        __syncthreads();

        // ---- phase B (warp 0): scalar chain + small-state updates
        if (warp == 0) {
            float S1 = red_s1[0] + red_s1[1] + red_s1[2] + red_s1[3];
            float XX = red_xx[0] + red_xx[1] + red_xx[2] + red_xx[3];
            float PP = red_pp[0] + red_pp[1] + red_pp[2] + red_pp[3];

            // forward
            float a1s = sigmoidf(S1 + be1);
            float a2s = sigmoidf(1024.0f * a1s * q + be2);
            float z30 = fmaf(1024.0f * a2s, r0, b30);
            float z31 = fmaf(1024.0f * a2s, r1, b31);
            float a30 = sigmoidf(z30), a31 = sigmoidf(z31);
            float e0 = expf(-a30), e1 = expf(-a31);
            float se = wredu(e0 + e1);
            float net0 = e0 / se, net1 = e1 / se;
            float d30 = (tg0 - net0) * a30 * (1.0f - a30);
            float d31 = (tg1 - net1) * a31 * (1.0f - a31);
            float rd3 = wredu(r0 * d30 + r1 * d31);      // (w3 @ d3) scalar
            float o2s = rd3 * a2s * (1.0f - a2s);
            float o1s = 1024.0f * q * o2s * a1s * (1.0f - a1s);
            float lamN = LR * o1s;

            // prefetch next targets while chain finishes
            float tgn0 = tg0, tgn1 = tg1;
            if (t + 1 < N_SAMPLES) {
                tgn0 = T[(size_t)(t + 1) * OUT_DIM + lane];
                tgn1 = T[(size_t)(t + 1) * OUT_DIM + 32 + lane];
            }

            // updates (gradients all use pre-update weights)
            float rp0  = fmaf(-LR * a2s, d30, r0);
            float rp1  = fmaf(-LR * a2s, d31, r1);
            float b3p0 = fmaf(-LR, d30, b30);
            float b3p1 = fmaf(-LR, d31, b31);
            float sr = wredu(rp0 * rp0 + rp1 * rp1);
            float sb = wredu(b3p0 * b3p0 + b3p1 * b3p1);
            float wn3 = fmaxf(sqrtf(1024.0f * sr), EPSN);   // sum over 1024 identical rows
            float bn3 = fmaxf(sqrtf(sb), EPSN);
            r0 = rp0 / wn3;  r1 = rp1 / wn3;
            b30 = b3p0 / bn3; b31 = b3p1 / bn3;

            float qp = q - LR * a1s * o2s;
            q = qp / fmaxf(sqrtf(1048576.0f * qp * qp), EPSN);  // 1024*1024 entries
            float b2p = be2 - LR * o2s;
            be2 = b2p / fmaxf(sqrtf(1024.0f * b2p * b2p), EPSN);
            float b1p = be1 - LR * o1s;
            be1 = b1p / fmaxf(sqrtf(1024.0f * b1p * b1p), EPSN);

            // ||p - lamN*x||^2 analytically from this step's fused reduction
            float ppn = fmaf(lamN * lamN, XX, fmaf(-2.0f * lamN, S1, PP));
            float wn1 = fmaxf(sqrtf(1024.0f * ppn), EPSN);
            if (lane == 0) { s_lam = lamN; s_wn = wn1; }

            tg0 = tgn0; tg1 = tgn1;
        }
        __syncthreads();
    }

    // apply final pending p update and stage results
    {
        float lam = s_lam, wn = s_wn;
#pragma unroll
        for (int k = 0; k < 8; k++) {
            g_p[tid * 8 + k] = (p[k] - lam * xp[k]) / wn;
        }
    }
    if (warp == 0) {
        g_r[lane] = r0; g_r[32 + lane] = r1;
        if (lane == 0) g_q = q;
    }
}

// Reconstruct full w1 | w2 | w3 into d_out (float4 stores).
__global__ void fill_kernel(float4* __restrict__ out)
{
    const int W1_4 = (IN_DIM * HID) / 4;          // 262144
    const int W2_4 = W1_4 + (HID * HID) / 4;      // 524288
    const int TOT4 = W2_4 + (HID * OUT_DIM) / 4;  // 540672

    int k = blockIdx.x * blockDim.x + threadIdx.x;
    if (k >= TOT4) return;

    if (k < W1_4) {
        float v = g_p[k >> 8];                    // i = (4k)/1024
        out[k] = make_float4(v, v, v, v);
    } else if (k < W2_4) {
        float v = g_q;
        out[k] = make_float4(v, v, v, v);
    } else {
        int m = k - W2_4;
        int j = (m & 15) * 4;                     // (4m) % 64
        out[k] = make_float4(g_r[j], g_r[j + 1], g_r[j + 2], g_r[j + 3]);
    }
}

extern "C" void kernel_launch(void* const* d_in, const int* in_sizes, int n_in,
                              void* d_out, int out_size)
{
    const float* X  = (const float*)d_in[0];
    const float* T  = (const float*)d_in[1];
    const float* w1 = (const float*)d_in[2];
    const float* b1 = (const float*)d_in[3];
    const float* w2 = (const float*)d_in[4];
    const float* b2 = (const float*)d_in[5];
    const float* w3 = (const float*)d_in[6];
    const float* b3 = (const float*)d_in[7];

    train_kernel<<<1, 128>>>(X, T, w1, b1, w2, b2, w3, b3);

    const int tot4 = (IN_DIM * HID + HID * HID + HID * OUT_DIM) / 4;  // 540672
    fill_kernel<<<(tot4 + 255) / 256, 256>>>((float4*)d_out);
}

// round 2
// speedup vs baseline: 2.5868x; 2.5868x over previous
#include <cuda_runtime.h>
#include <math.h>

#define N_SAMPLES 16384
#define IN_DIM    1024
#define HID       1024
#define OUT_DIM   64
#define LR        0.01f

// Staging for results between kernels (no allocs allowed).
__device__ float g_p[IN_DIM];
__device__ float g_r[OUT_DIM];
__device__ float g_q;

__device__ __forceinline__ float sigf(float z) {
    // fast sigmoid: MUFU.EX2 + MUFU.RCP based
    return __fdividef(1.0f, 1.0f + __expf(-z));
}

__device__ __forceinline__ void wtree3(float& a, float& b, float& c) {
#pragma unroll
    for (int o = 16; o; o >>= 1) {
        a += __shfl_xor_sync(0xffffffffu, a, o);
        b += __shfl_xor_sync(0xffffffffu, b, o);
        c += __shfl_xor_sync(0xffffffffu, c, o);
    }
}

__device__ __forceinline__ void wtree2(float& a, float& b) {
#pragma unroll
    for (int o = 16; o; o >>= 1) {
        a += __shfl_xor_sync(0xffffffffu, a, o);
        b += __shfl_xor_sync(0xffffffffu, b, o);
    }
}

// Warp-specialized pipelined trainer: 160 threads.
//   warp 0      : scalar chain for step t (uses reductions produced last iter)
//   warps 1..4  : p-update + reductions for step t+1 (A=x_{t+1}.p_t, B=x_{t+1}.x_t, XX)
// One __syncthreads per step; double-buffered shared exchange.
// Invariants: w1 = p ⊗ 1, w2 = q·1⊗1, w3 = 1 ⊗ r, b1 = β1·1, b2 = β2·1.
__global__ void __launch_bounds__(160, 1)
train_kernel(const float* __restrict__ X,      // [16384,1024]
             const float* __restrict__ T,      // [16384,64]
             const float* __restrict__ w1_in,
             const float* __restrict__ b1_in,
             const float* __restrict__ w2_in,
             const float* __restrict__ b2_in,
             const float* __restrict__ w3_in,
             const float* __restrict__ b3_in)
{
    __shared__ float sA[2][4], sB[2][4], sXX[2][4], sPP[4];
    __shared__ float sLam[2], sWn[2];

    const int tid  = threadIdx.x;
    const int lane = tid & 31;
    const int warp = tid >> 5;

    if (warp == 0) {
        // ------------- scalar engine -------------
        float r0  = w3_in[lane],  r1  = w3_in[32 + lane];   // row 0 (rows identical)
        float b30 = b3_in[lane],  b31 = b3_in[32 + lane];
        float q   = w2_in[0], be1 = b1_in[0], be2 = b2_in[0];
        float tg0 = T[lane],  tg1 = T[32 + lane];
        float lam = 0.0f, rwn = 1.0f, PP;
        if (lane == 0) { sLam[1] = 0.0f; sWn[1] = 1.0f; }
        __syncthreads();                                    // matches vector prologue
        PP = sPP[0] + sPP[1] + sPP[2] + sPP[3];             // ||p_0||^2

        for (int t = 0; t < N_SAMPLES; ++t) {
            const int b = t & 1;
            float A  = sA[b][0]  + sA[b][1]  + sA[b][2]  + sA[b][3];
            float B  = sB[b][0]  + sB[b][1]  + sB[b][2]  + sB[b][3];
            float XX = sXX[b][0] + sXX[b][1] + sXX[b][2] + sXX[b][3];

            // forward (uniform hidden layers)
            float S1  = (A - lam * B) * rwn;                // x_t . p_t
            float a1s = sigf(S1 + be1);
            float a2s = sigf(fmaf(1024.0f * a1s, q, be2));
            float h   = 1024.0f * a2s;
            float a30 = sigf(fmaf(h, r0, b30));
            float a31 = sigf(fmaf(h, r1, b31));
            float da30 = a30 * (1.0f - a30), da31 = a31 * (1.0f - a31);
            float e0 = __expf(-a30), e1 = __expf(-a31);

            // one interleaved tree gives se, and rd3 = u - v/se
            float se = e0 + e1;
            float u  = r0 * tg0 * da30 + r1 * tg1 * da31;
            float v  = r0 * e0  * da30 + r1 * e1  * da31;
            wtree3(se, u, v);
            float rse = __fdividef(1.0f, se);
            float rd3 = u - v * rse;
            float o2s = rd3 * a2s * (1.0f - a2s);
            float o1s = 1024.0f * q * o2s * a1s * (1.0f - a1s);
            float lamN = LR * o1s;

            // analytic ||p - lamN x||^2 and norm; publish ASAP for vector warps
            float ppn = fmaf(lamN * lamN, XX, fmaf(-2.0f * lamN, S1, PP));
            float wnN = sqrtf(1024.0f * ppn);
            if (lane == 0) { sLam[b] = lamN; sWn[b] = wnN; }

            // tail: per-output gradient + small-state updates
            float d30 = (tg0 - e0 * rse) * da30;
            float d31 = (tg1 - e1 * rse) * da31;
            float rp0 = fmaf(-LR * a2s, d30, r0);
            float rp1 = fmaf(-LR * a2s, d31, r1);
            float bp0 = fmaf(-LR, d30, b30);
            float bp1 = fmaf(-LR, d31, b31);
            float sr = rp0 * rp0 + rp1 * rp1;
            float sb = bp0 * bp0 + bp1 * bp1;

            // prefetch next targets while trees run
            float tn0 = tg0, tn1 = tg1;
            if (t + 1 < N_SAMPLES) {
                tn0 = T[(size_t)(t + 1) * OUT_DIM + lane];
                tn1 = T[(size_t)(t + 1) * OUT_DIM + 32 + lane];
            }

            wtree2(sr, sb);
            float ir = rsqrtf(1024.0f * sr);                // 1/||w3||_F
            float ib = rsqrtf(sb);
            r0 = rp0 * ir;  r1 = rp1 * ir;
            b30 = bp0 * ib; b31 = bp1 * ib;

            // uniform tensors normalize to exact +/- constants
            q   = copysignf(1.0f / 1024.0f, fmaf(-LR * a1s, o2s, q));
            be2 = copysignf(0.03125f, fmaf(-LR, o2s, be2));
            be1 = copysignf(0.03125f, fmaf(-LR, o1s, be1));

            lam = lamN;
            rwn = 1.0f / wnN;
            PP  = __fdividef(ppn, wnN * wnN);               // ||p_{t+1}||^2
            tg0 = tn0; tg1 = tn1;
            __syncthreads();
        }
        g_r[lane] = r0; g_r[32 + lane] = r1;
        if (lane == 0) g_q = q;
    } else {
        // ------------- vector engine: 128 threads, 8 elems each -------------
        const int vid = tid - 32;
        float p[8], xp[8], xc[8], xn[8];
#pragma unroll
        for (int k = 0; k < 8; k++) {
            p[k]  = w1_in[(size_t)(vid * 8 + k) * HID];     // column 0
            xp[k] = 0.0f;
            xc[k] = X[vid * 8 + k];                         // x_0
        }
        {   // xn = x_1
            const float4* q4 = (const float4*)(X + IN_DIM + vid * 8);
            float4 a = q4[0], b = q4[1];
            xn[0]=a.x; xn[1]=a.y; xn[2]=a.z; xn[3]=a.w;
            xn[4]=b.x; xn[5]=b.y; xn[6]=b.z; xn[7]=b.w;
        }
        // prologue reductions for step 0: A0 = x0.p0, XX0, PP0  (B0 = 0, lam_{-1}=0)
        float A = 0.0f, XXv = 0.0f, PPv = 0.0f;
#pragma unroll
        for (int k = 0; k < 8; k++) {
            A   = fmaf(xc[k], p[k], A);
            XXv = fmaf(xc[k], xc[k], XXv);
            PPv = fmaf(p[k],  p[k],  PPv);
        }
        wtree3(A, XXv, PPv);
        if (lane == 0) {
            sA[0][warp - 1] = A; sB[0][warp - 1] = 0.0f;
            sXX[0][warp - 1] = XXv; sPP[warp - 1] = PPv;
        }
        __syncthreads();

        for (int t = 0; t < N_SAMPLES; ++t) {
            // issue x_{t+2} load early (2-step prefetch hides DRAM latency)
            float4 La, Lb;
            const bool ld = (t + 2 < N_SAMPLES);
            if (ld) {
                const float4* q4 = (const float4*)(X + (size_t)(t + 2) * IN_DIM + vid * 8);
                La = q4[0]; Lb = q4[1];
            }
            const float lam = sLam[1 - (t & 1)];            // lambda_{t-1}
            const float wn  = sWn[1 - (t & 1)];
            const float rw  = 1.0f / wn;

            float a = 0.0f, bb = 0.0f, xx = 0.0f;
#pragma unroll
            for (int k = 0; k < 8; k++) {
                float pk = fmaf(-lam, xp[k], p[k]) * rw;    // p_{t-1} -> p_t
                p[k] = pk;
                a  = fmaf(xn[k], pk,    a);                 // x_{t+1}.p_t
                bb = fmaf(xn[k], xc[k], bb);                // x_{t+1}.x_t
                xx = fmaf(xn[k], xn[k], xx);                // ||x_{t+1}||^2
            }
            wtree3(a, bb, xx);
            const int bw = (t + 1) & 1;
            if (lane == 0) { sA[bw][warp-1] = a; sB[bw][warp-1] = bb; sXX[bw][warp-1] = xx; }
#pragma unroll
            for (int k = 0; k < 8; k++) { xp[k] = xc[k]; xc[k] = xn[k]; }
            if (ld) {
                xn[0]=La.x; xn[1]=La.y; xn[2]=La.z; xn[3]=La.w;
                xn[4]=Lb.x; xn[5]=Lb.y; xn[6]=Lb.z; xn[7]=Lb.w;
            }
            __syncthreads();
        }
        // apply final pending update: p_N = (p_{N-1} - lam_{N-1} x_{N-1}) / wn
        const float lam = sLam[(N_SAMPLES - 1) & 1];
        const float rw  = 1.0f / sWn[(N_SAMPLES - 1) & 1];
#pragma unroll
        for (int k = 0; k < 8; k++)
            g_p[vid * 8 + k] = fmaf(-lam, xp[k], p[k]) * rw;
    }
}

// Reconstruct full w1 | w2 | w3 into d_out (float4 stores).
__global__ void fill_kernel(float4* __restrict__ out)
{
    const int W1_4 = (IN_DIM * HID) / 4;          // 262144
    const int W2_4 = W1_4 + (HID * HID) / 4;      // 524288
    const int TOT4 = W2_4 + (HID * OUT_DIM) / 4;  // 540672

    int k = blockIdx.x * blockDim.x + threadIdx.x;
    if (k >= TOT4) return;

    if (k < W1_4) {
        float v = g_p[k >> 8];
        out[k] = make_float4(v, v, v, v);
    } else if (k < W2_4) {
        float v = g_q;
        out[k] = make_float4(v, v, v, v);
    } else {
        int m = k - W2_4;
        int j = (m & 15) * 4;
        out[k] = make_float4(g_r[j], g_r[j + 1], g_r[j + 2], g_r[j + 3]);
    }
}

extern "C" void kernel_launch(void* const* d_in, const int* in_sizes, int n_in,
                              void* d_out, int out_size)
{
    const float* X  = (const float*)d_in[0];
    const float* T  = (const float*)d_in[1];
    const float* w1 = (const float*)d_in[2];
    const float* b1 = (const float*)d_in[3];
    const float* w2 = (const float*)d_in[4];
    const float* b2 = (const float*)d_in[5];
    const float* w3 = (const float*)d_in[6];
    const float* b3 = (const float*)d_in[7];

    train_kernel<<<1, 160>>>(X, T, w1, b1, w2, b2, w3, b3);

    const int tot4 = (IN_DIM * HID + HID * HID + HID * OUT_DIM) / 4;  // 540672
    fill_kernel<<<(tot4 + 255) / 256, 256>>>((float4*)d_out);
}

// round 4
// speedup vs baseline: 3.2376x; 1.2516x over previous
#include <cuda_runtime.h>
#include <math.h>

#define N_SAMPLES 16384
#define IN_DIM    1024
#define HID       1024
#define OUT_DIM   64
#define LR        0.01f

// Staging / precomputed arrays (no allocs allowed).
__device__ float  g_p[IN_DIM];
__device__ float  g_r[OUT_DIM];
__device__ float  g_q;
__device__ float2 g_bx[N_SAMPLES];   // (B_t = x_t.x_{t-1}, XX_t = |x_t|^2)

__device__ __forceinline__ float sigf(float z) {
    return __fdividef(1.0f, 1.0f + __expf(-z));
}

// Interleaved warp reduction: N independent sums in one 5-level tree.
template <int N>
__device__ __forceinline__ void wtree(float (&v)[N]) {
#pragma unroll
    for (int o = 16; o; o >>= 1) {
        float tmp[N];
#pragma unroll
        for (int i = 0; i < N; i++) tmp[i] = __shfl_xor_sync(0xffffffffu, v[i], o);
#pragma unroll
        for (int i = 0; i < N; i++) v[i] += tmp[i];
    }
}

__device__ __forceinline__ float wtree1(float a) {
#pragma unroll
    for (int o = 16; o; o >>= 1) a += __shfl_xor_sync(0xffffffffu, a, o);
    return a;
}

// Named-barrier split sync (block of 160 threads = 5 warps).
#define BAR_ARRIVE1() asm volatile("bar.arrive 1, 160;" ::: "memory")
#define BAR_SYNC1()   asm volatile("bar.sync   1, 160;" ::: "memory")
#define BAR_ARRIVE2() asm volatile("bar.arrive 2, 160;" ::: "memory")
#define BAR_SYNC2()   asm volatile("bar.sync   2, 160;" ::: "memory")

// Pre-pass: per-row self/neighbor dots, training-independent.
__global__ void pre_kernel(const float* __restrict__ X)
{
    const int t = blockIdx.x;
    const int tid = threadIdx.x;             // 128 threads
    const float4* xt = (const float4*)(X + (size_t)t * IN_DIM);
    const float4* xm = (const float4*)(X + (size_t)(t ? t - 1 : 0) * IN_DIM);
    float s[2] = {0.0f, 0.0f};
#pragma unroll
    for (int i = 0; i < 2; i++) {
        float4 a = xt[tid + 128 * i];
        float4 c = xm[tid + 128 * i];
        s[0] = fmaf(a.x, a.x, fmaf(a.y, a.y, fmaf(a.z, a.z, fmaf(a.w, a.w, s[0]))));
        s[1] = fmaf(a.x, c.x, fmaf(a.y, c.y, fmaf(a.z, c.z, fmaf(a.w, c.w, s[1]))));
    }
    wtree<2>(s);
    __shared__ float sh[8];
    const int w = tid >> 5;
    if ((tid & 31) == 0) { sh[w] = s[0]; sh[4 + w] = s[1]; }
    __syncthreads();
    if (tid == 0) {
        float XX = sh[0] + sh[1] + sh[2] + sh[3];
        float B  = t ? (sh[4] + sh[5] + sh[6] + sh[7]) : 0.0f;
        g_bx[t] = make_float2(B, XX);
    }
}

// Warp-specialized pipelined trainer: 160 threads.
//   warp 0     : scalar chain for step t   (producer of lam/rwn  -> barrier 2)
//   warps 1..4 : A_{t+1} = x_{t+1}.p_t     (producer of A        -> barrier 1)
// Invariants: w1 = p ⊗ 1, w2 = q·1⊗1, w3 = 1 ⊗ r, b1 = β1·1, b2 = β2·1.
__global__ void __launch_bounds__(160, 1)
train_kernel(const float* __restrict__ X,
             const float* __restrict__ T,
             const float* __restrict__ w1_in,
             const float* __restrict__ b1_in,
             const float* __restrict__ w2_in,
             const float* __restrict__ b2_in,
             const float* __restrict__ w3_in,
             const float* __restrict__ b3_in)
{
    __shared__ float4 sA4[2];     // per-warp partial A sums, double-buffered
    __shared__ float  sPP[4];
    __shared__ float2 sLR[2];     // (lam, rwn), double-buffered

    const int tid  = threadIdx.x;
    const int lane = tid & 31;
    const int warp = tid >> 5;

    if (warp == 0) {
        // ---------------- scalar engine ----------------
        float r0  = w3_in[lane],  r1  = w3_in[32 + lane];
        float b30 = b3_in[lane],  b31 = b3_in[32 + lane];
        float q   = w2_in[0], be1 = b1_in[0], be2 = b2_in[0];
        float tg0 = T[lane],  tg1 = T[32 + lane];
        float in2[2] = { r0 * r0 + r1 * r1, b30 * b30 + b31 * b31 };
        wtree<2>(in2);
        float SR = in2[0], SB = in2[1];
        float lam = 0.0f, rwn = 1.0f, PP = 0.0f;
        float2 bxc = g_bx[0];
        float2 bxn = g_bx[1];
        if (lane == 0) sLR[1] = make_float2(0.0f, 1.0f);
        BAR_ARRIVE2();

        for (int t = 0; t < N_SAMPLES; ++t) {
            const int b = t & 1;
            BAR_SYNC1();                              // A_t ready
            float4 av = sA4[b];
            if (t == 0) PP = sPP[0] + sPP[1] + sPP[2] + sPP[3];
            float2 bx2 = make_float2(0.0f, 0.0f);     // prefetch (B,XX) for t+2
            if (t + 2 < N_SAMPLES) bx2 = g_bx[t + 2];

            float A   = (av.x + av.y) + (av.z + av.w);
            float S1  = (A - lam * bxc.x) * rwn;      // x_t . p_t
            float a1s = sigf(S1 + be1);
            float a2s = sigf(fmaf(1024.0f * q, a1s, be2));
            float h   = 1024.0f * a2s;
            float a30 = sigf(fmaf(h, r0, b30));
            float a31 = sigf(fmaf(h, r1, b31));
            float da30 = a30 * (1.0f - a30), da31 = a31 * (1.0f - a31);
            float e0 = __expf(-a30), e1 = __expf(-a31);
            float al0 = tg0 * da30, al1 = tg1 * da31; // alpha = t*da3
            float bt0 = e0 * da30,  bt1 = e1 * da31;  // beta  = e*da3

            // single batched reduction round: 8 sums in one interleaved tree
            float s8[8];
            s8[0] = e0 + e1;                          // se
            s8[1] = r0 * al0 + r1 * al1;              // u
            s8[2] = r0 * bt0 + r1 * bt1;              // v
            s8[3] = al0 * al0 + al1 * al1;            // saa
            s8[4] = al0 * bt0 + al1 * bt1;            // sab
            s8[5] = bt0 * bt0 + bt1 * bt1;            // sbb
            s8[6] = b30 * al0 + b31 * al1;            // sba
            s8[7] = b30 * bt0 + b31 * bt1;            // sbt
            wtree<8>(s8);

            float rse = __fdividef(1.0f, s8[0]);
            float rd3 = fmaf(-s8[2], rse, s8[1]);     // sum r*d3
            float o2s = rd3 * a2s * (1.0f - a2s);
            float o1s = 1024.0f * q * o2s * a1s * (1.0f - a1s);
            float lamN = LR * o1s;
            float ppn  = fmaf(lamN * lamN, bxc.y, fmaf(-2.0f * lamN, S1, PP));
            float rwnN = rsqrtf(1024.0f * ppn);
            if (lane == 0) sLR[b] = make_float2(lamN, rwnN);
            BAR_ARRIVE2();                            // lam_t / rwn_t published

            // -------- tail (overlaps vector warps' next dot) --------
            float tn0 = tg0, tn1 = tg1;
            if (t + 1 < N_SAMPLES) {
                tn0 = T[(size_t)(t + 1) * OUT_DIM + lane];
                tn1 = T[(size_t)(t + 1) * OUT_DIM + 32 + lane];
            }
            float d30 = fmaf(-bt0, rse, al0);
            float d31 = fmaf(-bt1, rse, al1);
            float Sd3 = fmaf(rse * rse, s8[5], fmaf(-2.0f * rse, s8[4], s8[3]));
            float la2 = LR * a2s;
            float srp = fmaf(la2 * la2, Sd3, fmaf(-2.0f * la2, rd3, SR));  // sum r'^2
            float Sbd = fmaf(-rse, s8[7], s8[6]);                          // sum b3*d3
            float sbp = fmaf(LR * LR, Sd3, fmaf(-2.0f * LR, Sbd, SB));     // sum b3'^2
            float ir  = rsqrtf(1024.0f * srp);
            float ib  = rsqrtf(sbp);
            r0  = fmaf(-la2, d30, r0) * ir;
            r1  = fmaf(-la2, d31, r1) * ir;
            b30 = fmaf(-LR, d30, b30) * ib;
            b31 = fmaf(-LR, d31, b31) * ib;
            SR  = srp * ir * ir;
            SB  = sbp * ib * ib;
            q   = copysignf(1.0f / 1024.0f, fmaf(-LR * a1s, o2s, q));
            be2 = copysignf(0.03125f, fmaf(-LR, o2s, be2));
            be1 = copysignf(0.03125f, fmaf(-LR, o1s, be1));
            PP  = ppn * rwnN * rwnN;
            lam = lamN; rwn = rwnN;
            bxc = bxn;  bxn = bx2;
            tg0 = tn0;  tg1 = tn1;
        }
        g_r[lane] = r0; g_r[32 + lane] = r1;
        if (lane == 0) g_q = q;
    } else {
        // ---------------- vector engine: 128 threads, 8 elems each ----------------
        const int vid = tid - 32;
        float p[8], xp[8], xc[8], xn[8];
#pragma unroll
        for (int k = 0; k < 8; k++) {
            p[k]  = w1_in[(size_t)(vid * 8 + k) * HID];
            xp[k] = 0.0f;
            xc[k] = X[vid * 8 + k];
        }
        {
            const float4* q4 = (const float4*)(X + IN_DIM + vid * 8);
            float4 a = q4[0], b = q4[1];
            xn[0]=a.x; xn[1]=a.y; xn[2]=a.z; xn[3]=a.w;
            xn[4]=b.x; xn[5]=b.y; xn[6]=b.z; xn[7]=b.w;
        }
        float pr[2] = {0.0f, 0.0f};
#pragma unroll
        for (int k = 0; k < 8; k++) {
            pr[0] = fmaf(xc[k], p[k], pr[0]);   // A_0
            pr[1] = fmaf(p[k],  p[k], pr[1]);   // PP_0
        }
        wtree<2>(pr);
        if (lane == 0) { ((float*)&sA4[0])[warp - 1] = pr[0]; sPP[warp - 1] = pr[1]; }
        BAR_ARRIVE1();

        for (int t = 0; t < N_SAMPLES; ++t) {
            float4 La, Lb;
            const bool ld = (t + 2 < N_SAMPLES);
            if (ld) {   // issue 2-ahead prefetch before waiting
                const float4* q4 = (const float4*)(X + (size_t)(t + 2) * IN_DIM + vid * 8);
                La = q4[0]; Lb = q4[1];
            }
            BAR_SYNC2();                                // lam_{t-1} ready
            float2 lr = sLR[1 - (t & 1)];
            float a = 0.0f;
#pragma unroll
            for (int k = 0; k < 8; k++) {
                float pk = fmaf(-lr.x, xp[k], p[k]) * lr.y;   // p_{t-1} -> p_t
                p[k] = pk;
                a = fmaf(xn[k], pk, a);                        // x_{t+1}.p_t
            }
            a = wtree1(a);
            if (lane == 0) ((float*)&sA4[(t + 1) & 1])[warp - 1] = a;
            BAR_ARRIVE1();
#pragma unroll
            for (int k = 0; k < 8; k++) { xp[k] = xc[k]; xc[k] = xn[k]; }
            if (ld) {
                xn[0]=La.x; xn[1]=La.y; xn[2]=La.z; xn[3]=La.w;
                xn[4]=Lb.x; xn[5]=Lb.y; xn[6]=Lb.z; xn[7]=Lb.w;
            }
        }
        BAR_SYNC2();                                    // final lam_{N-1}
        float2 lr = sLR[(N_SAMPLES - 1) & 1];
#pragma unroll
        for (int k = 0; k < 8; k++)
            g_p[vid * 8 + k] = fmaf(-lr.x, xp[k], p[k]) * lr.y;
    }
}

// Reconstruct full w1 | w2 | w3 into d_out (float4 stores).
__global__ void fill_kernel(float4* __restrict__ out)
{
    const int W1_4 = (IN_DIM * HID) / 4;
    const int W2_4 = W1_4 + (HID * HID) / 4;
    const int TOT4 = W2_4 + (HID * OUT_DIM) / 4;

    int k = blockIdx.x * blockDim.x + threadIdx.x;
    if (k >= TOT4) return;

    if (k < W1_4) {
        float v = g_p[k >> 8];
        out[k] = make_float4(v, v, v, v);
    } else if (k < W2_4) {
        float v = g_q;
        out[k] = make_float4(v, v, v, v);
    } else {
        int m = k - W2_4;
        int j = (m & 15) * 4;
        out[k] = make_float4(g_r[j], g_r[j + 1], g_r[j + 2], g_r[j + 3]);
    }
}

extern "C" void kernel_launch(void* const* d_in, const int* in_sizes, int n_in,
                              void* d_out, int out_size)
{
    const float* X  = (const float*)d_in[0];
    const float* T  = (const float*)d_in[1];
    const float* w1 = (const float*)d_in[2];
    const float* b1 = (const float*)d_in[3];
    const float* w2 = (const float*)d_in[4];
    const float* b2 = (const float*)d_in[5];
    const float* w3 = (const float*)d_in[6];
    const float* b3 = (const float*)d_in[7];

    pre_kernel<<<N_SAMPLES, 128>>>(X);
    train_kernel<<<1, 160>>>(X, T, w1, b1, w2, b2, w3, b3);

    const int tot4 = (IN_DIM * HID + HID * HID + HID * OUT_DIM) / 4;
    fill_kernel<<<(tot4 + 255) / 256, 256>>>((float4*)d_out);
}